// round 9
// baseline (speedup 1.0000x reference)
#include <cuda_runtime.h>
#include <cuda_fp16.h>
#include <cstdint>
#include <cstddef>

// ---------------- problem constants ----------------
#define TSTEPS 256
#define BB 128      // batch
#define HH 512      // GRU hidden
#define LL 1024     // LSTM hidden
#define VV 1024     // vocab

// ---------------- config ----------------
#define NTH 1024
#define BM 128
#define PBK 64
#define ASTRH (PBK + 8)             // 72 halfs
#define WSTRH_G (HH + 8)            // 520 halfs
#define WSTRH_L (LL + 8)            // 1032 halfs
#define CSTR 68                     // fp32 staging stride (64 cols + pad)

// dynamic smem (halfs):
//  GRU : Ws[64][WSTRH_G]  + As[2][128][ASTRH]  = 103424 B
//  XG  : Ws[128][WSTRH_G] + As[2][128][ASTRH]  = 169984 B
//  LSTM: Ws[64][WSTRH_L]  + As[2][128][ASTRH]  = 168960 B
//  FC  : Bs[2][64][ASTRH] + As[2][128][ASTRH]  = 55296 B
#define SMEM_FUSED 169984
#define F_ATILE (2 * 64 * ASTRH)    // FC As offset (halfs)

// ---------------- persistent device scratch ----------------
__device__ __align__(256) __half g_Wgh  [2048 * 512];   // GRU combined W (t>=2), gate-interleaved
__device__ __align__(256) __half g_Wg1h [2048 * 512];   // GRU step-1 W (x=0 path)
__device__ __align__(256) float  g_bg   [2048];         // GRU combined bias
__device__ __align__(256) __half g_Wihlh[4096 * 512];   // LSTM Wih fp16, gate-interleaved
__device__ __align__(256) float  g_bl   [4096];         // LSTM bih+bhh, interleaved
__device__ __align__(256) __half g_Whhlh[4096 * 1024];  // LSTM Whh fp16, gate-interleaved
__device__ __align__(256) __half g_fcWh [1024 * 1024];  // fc weights fp16
__device__ __align__(256) float  g_x    [2 * BB * HH];  // GRU state fp32 ping-pong
__device__ __align__(256) __half g_xh   [2 * BB * HH];  // GRU state fp16 (operand)
__device__ __align__(256) __half g_zh   [BB * HH];      // half(z)
__device__ __align__(256) __half g_seqh [TSTEPS * BB * HH];          // relu(x_t) fp16
__device__ __align__(256) float  g_Xg   [(size_t)TSTEPS * BB * 4096];// LSTM input gates (+bias)
__device__ __align__(256) __half g_hh   [2 * BB * LL];  // LSTM h fp16 ping-pong
__device__ __align__(256) float  g_c    [BB * LL];      // LSTM c fp32
__device__ __align__(256) __half g_hsh  [(size_t)TSTEPS * BB * LL];  // LSTM outputs [T,B,L]
// barrier counters, each on its own 128B line
__device__ __align__(128) unsigned g_bar_gru[32];
__device__ __align__(128) unsigned g_bar_xg[32];
__device__ __align__(128) unsigned g_bar_lstm[32];
__device__ __align__(128) unsigned g_fc_cnt[32];

// ---------------- helpers ----------------
__device__ __forceinline__ void mma_f16(float4& d,
                                        uint32_t a0, uint32_t a1, uint32_t a2, uint32_t a3,
                                        uint32_t b0, uint32_t b1) {
    asm volatile(
        "mma.sync.aligned.m16n8k16.row.col.f32.f16.f16.f32 "
        "{%0,%1,%2,%3}, {%4,%5,%6,%7}, {%8,%9}, {%0,%1,%2,%3};\n"
        : "+f"(d.x), "+f"(d.y), "+f"(d.z), "+f"(d.w)
        : "r"(a0), "r"(a1), "r"(a2), "r"(a3), "r"(b0), "r"(b1));
}

__device__ __forceinline__ float sigf(float x) { return 1.0f / (1.0f + expf(-x)); }

// arrive: release-add (orders all prior writes), no full membar
__device__ __forceinline__ void bar_arrive(unsigned* bar) {
    __syncthreads();
    if (threadIdx.x == 0)
        asm volatile("red.release.gpu.global.add.u32 [%0], 1;" :: "l"(bar) : "memory");
}
// acquire spin
__device__ __forceinline__ void wait_ge(unsigned* bar, unsigned target) {
    if (threadIdx.x == 0) {
        unsigned v;
        do {
            asm volatile("ld.acquire.gpu.global.b32 %0, [%1];" : "=r"(v) : "l"(bar));
        } while (v < target);
    }
    __syncthreads();
}
// combined two-barrier wait (one poll loop)
__device__ __forceinline__ void wait_ge2(unsigned* barA, unsigned tA,
                                         unsigned* barB, unsigned tB) {
    if (threadIdx.x == 0) {
        unsigned va, vb;
        do {
            asm volatile("ld.acquire.gpu.global.b32 %0, [%1];" : "=r"(va) : "l"(barA));
            asm volatile("ld.acquire.gpu.global.b32 %0, [%1];" : "=r"(vb) : "l"(barB));
        } while (va < tA || vb < tB);
    }
    __syncthreads();
}

// A-tile [128][64 halfs] loaders, 1024 threads: 8 threads/row, 1 row per thread
__device__ __forceinline__ void a_load(const __half* __restrict__ A, int ldK, int k0,
                                       int tid, uint4* pr) {
    const int rL = tid >> 3, ch = (tid & 7) * 8;
    pr[0] = *(const uint4*)(A + (size_t)rL * ldK + k0 + ch);
}
__device__ __forceinline__ void a_store(__half* buf, int tid, const uint4* pr) {
    const int rL = tid >> 3, ch = (tid & 7) * 8;
    *(uint4*)(buf + rL * ASTRH + ch) = pr[0];
}

// one PBK=64 k-slab of mma (4 kk iters). Warp grid 8x4: wm = 16 rows, wn = NI*8 cols.
template <int NI>
__device__ __forceinline__ void do_kk4(const __half* __restrict__ Ac,
                                       const __half* __restrict__ Bbase,
                                       int wstr, int kg0,
                                       int lane, int wm, int wn,
                                       float4 (&acc)[NI]) {
#pragma unroll
    for (int kk = 0; kk < 4; kk++) {
        const int kb = kk * 16 + 2 * (lane & 3);
        const __half* ap = Ac + (wm * 16 + (lane >> 2)) * ASTRH + kb;
        const uint32_t a0 = *(const uint32_t*)(ap);
        const uint32_t a1 = *(const uint32_t*)(ap + 8 * ASTRH);
        const uint32_t a2 = *(const uint32_t*)(ap + 8);
        const uint32_t a3 = *(const uint32_t*)(ap + 8 * ASTRH + 8);
#pragma unroll
        for (int ni = 0; ni < NI; ni++) {
            const __half* wp = Bbase + (size_t)(wn * (NI * 8) + ni * 8 + (lane >> 2)) * wstr + kg0 + kb;
            const uint32_t b0 = *(const uint32_t*)(wp);
            const uint32_t b1 = *(const uint32_t*)(wp + 8);
            mma_f16(acc[ni], a0, a1, a2, a3, b0, b1);
        }
    }
}

// ============================================================================
// FC work-steal: logits tile [128 x 64] = hs_t @ fcW^T + fcb
// ============================================================================
__device__ void fc_worker(__half* smh, const float* __restrict__ fcb,
                          float* __restrict__ out) {
    __shared__ int s_tile;
    __half* Bs = smh;               // [2][64][ASTRH]
    __half* As = smh + F_ATILE;     // [2][128][ASTRH]

    const int tid  = threadIdx.x;
    const int lane = tid & 31;
    const int wid  = tid >> 5;
    const int wm   = wid & 7;       // 0..7, 16 rows each
    const int wn   = wid >> 3;      // 0..3, 16 cols each

    while (true) {
        __syncthreads();
        if (tid == 0) s_tile = (int)atomicAdd(&g_fc_cnt[0], 1u);
        __syncthreads();
        const int tile = s_tile;
        if (tile >= TSTEPS * 16) return;
        const int t  = tile >> 4;
        const int n0 = (tile & 15) * 64;
        wait_ge(g_bar_lstm, 64u * (unsigned)(t + 1));

        const __half* Abh = g_hsh  + (size_t)t * BB * LL;
        const __half* Wb  = g_fcWh + (size_t)n0 * LL;

        float4 acc[2];
#pragma unroll
        for (int ni = 0; ni < 2; ni++) acc[ni] = make_float4(0.f, 0.f, 0.f, 0.f);

        uint4 pr[1], qr;
        a_load(Abh, LL, 0, tid, pr);
        if (tid < 512) {
            const int r = tid >> 3, cb = (tid & 7) * 8;
            qr = *(const uint4*)(Wb + (size_t)r * LL + cb);
        }
        a_store(As, tid, pr);
        if (tid < 512) {
            const int r = tid >> 3, cb = (tid & 7) * 8;
            *(uint4*)(Bs + r * ASTRH + cb) = qr;
        }
        __syncthreads();

        for (int kt = 0; kt < 16; ++kt) {
            const int  cur  = kt & 1;
            const bool more = (kt + 1 < 16);
            if (more) {
                const int k0 = (kt + 1) * PBK;
                a_load(Abh, LL, k0, tid, pr);
                if (tid < 512) {
                    const int r = tid >> 3, cb = (tid & 7) * 8;
                    qr = *(const uint4*)(Wb + (size_t)r * LL + k0 + cb);
                }
            }
            do_kk4<2>(As + cur * BM * ASTRH, Bs + cur * 64 * ASTRH,
                      ASTRH, 0, lane, wm, wn, acc);
            if (more) {
                const int nxt = cur ^ 1;
                a_store(As + nxt * BM * ASTRH, tid, pr);
                if (tid < 512) {
                    const int r = tid >> 3, cb = (tid & 7) * 8;
                    *(uint4*)(Bs + nxt * 64 * ASTRH + r * ASTRH + cb) = qr;
                }
            }
            __syncthreads();
        }

#pragma unroll
        for (int ni = 0; ni < 2; ni++) {
            const int r   = wm * 16 + (lane >> 2);
            const int col = n0 + wn * 16 + ni * 8 + 2 * (lane & 3);
            const float b0 = fcb[col], b1 = fcb[col + 1];
            float* o0 = out + ((size_t)r * TSTEPS + t) * VV + col;
            float* o1 = out + ((size_t)(r + 8) * TSTEPS + t) * VV + col;
            *(float2*)o0 = make_float2(acc[ni].x + b0, acc[ni].y + b1);
            *(float2*)o1 = make_float2(acc[ni].z + b0, acc[ni].w + b1);
        }
    }
}

// ============================================================================
// Fused pipelined kernel, grid = 148 (all co-resident, 1024 thr = 32 warps/SM):
//   bid 0-31:    GRU chain, 64 cols each
//   bid 32-63:   XG, 128 cols each (one step behind GRU)
//   bid 64-127:  LSTM chain, 64 cols each (consumes Xg[t])
//   bid 128-147: FC work-steal (chain CTAs join at the end)
// ============================================================================
__global__ void __launch_bounds__(NTH)
fused_persist(const float* __restrict__ z, const float* __restrict__ fcb,
              float* __restrict__ out) {
    extern __shared__ __half smh[];
    const int tid  = threadIdx.x;
    const int lane = tid & 31;
    const int wid  = tid >> 5;
    const int wm   = wid & 7;       // 0..7 (16 rows)
    const int wn   = wid >> 3;      // 0..3
    const int bid  = blockIdx.x;

    if (bid < 32) {
        // ================= GRU chain: 64 cols (16 units) =================
        __half* Ws = smh;                     // [64][WSTRH_G]
        __half* As = smh + 64 * WSTRH_G;      // [2][128][ASTRH]
        float*  Cs = (float*)As;              // staging, stride CSTR
        const int n0 = bid * 64;

        for (int i = tid; i < 64 * 64; i += NTH) {
            const int r = i >> 6, c = (i & 63) * 8;
            *(uint4*)(Ws + r * WSTRH_G + c) = *(const uint4*)(g_Wg1h + (size_t)(n0 + r) * HH + c);
        }
        __syncthreads();

        for (int t = 1; t < TSTEPS; ++t) {
            const __half* Abh  = (t == 1) ? g_zh : g_xh + (size_t)((t - 1) & 1) * BB * HH;
            const float*  hp32 = (t == 1) ? z    : g_x  + (size_t)((t - 1) & 1) * BB * HH;
            float*  xo32 = g_x    + (size_t)(t & 1) * BB * HH;
            __half* xoh  = g_xh   + (size_t)(t & 1) * BB * HH;
            __half* so   = g_seqh + (size_t)t * BB * HH;

            float hp[2];
#pragma unroll
            for (int s = 0; s < 2; s++) {
                const int it = tid + s * NTH;
                hp[s] = hp32[(size_t)(it >> 4) * HH + (n0 >> 2) + (it & 15)];
            }

            float4 acc[2];
#pragma unroll
            for (int ni = 0; ni < 2; ni++) acc[ni] = make_float4(0.f, 0.f, 0.f, 0.f);

            uint4 pr[1];
            a_load(Abh, HH, 0, tid, pr);
            a_store(As, tid, pr);
            __syncthreads();
            for (int kt = 0; kt < 8; ++kt) {
                const int  cur  = kt & 1;
                const bool more = (kt + 1 < 8);
                if (more) a_load(Abh, HH, (kt + 1) * PBK, tid, pr);
                do_kk4<2>(As + cur * BM * ASTRH, Ws, WSTRH_G, kt * PBK, lane, wm, wn, acc);
                if (more) a_store(As + ((kt + 1) & 1) * BM * ASTRH, tid, pr);
                __syncthreads();
            }

#pragma unroll
            for (int ni = 0; ni < 2; ni++) {
                const int r = wm * 16 + (lane >> 2);
                const int c = wn * 16 + ni * 8 + 2 * (lane & 3);
                const float b0 = g_bg[n0 + c], b1 = g_bg[n0 + c + 1];
                Cs[r * CSTR + c]           = acc[ni].x + b0;
                Cs[r * CSTR + c + 1]       = acc[ni].y + b1;
                Cs[(r + 8) * CSTR + c]     = acc[ni].z + b0;
                Cs[(r + 8) * CSTR + c + 1] = acc[ni].w + b1;
            }
            __syncthreads();

#pragma unroll
            for (int s = 0; s < 2; s++) {
                const int it  = tid + s * NTH;
                const int u   = it & 15;
                const int row = it >> 4;
                const int jg  = (n0 >> 2) + u;
                const float4 cv = *(const float4*)(Cs + row * CSTR + 4 * u);
                const float rg = sigf(cv.x);
                const float zg = sigf(cv.y);
                const float nn = tanhf(cv.z + rg * cv.w);
                const float xn = (1.f - zg) * nn + zg * hp[s];
                const int oi = row * HH + jg;
                xo32[oi] = xn;
                xoh[oi]  = __float2half_rn(xn);
                so[oi]   = __float2half_rn(fmaxf(xn, 0.f));
            }

            bar_arrive(g_bar_gru);
            if (t < TSTEPS - 1) {
                wait_ge(g_bar_gru, 32u * (unsigned)t);
                if (t == 1) {   // swap to combined weights for t >= 2
                    for (int i = tid; i < 64 * 64; i += NTH) {
                        const int r = i >> 6, c = (i & 63) * 8;
                        *(uint4*)(Ws + r * WSTRH_G + c) =
                            *(const uint4*)(g_Wgh + (size_t)(n0 + r) * HH + c);
                    }
                    __syncthreads();
                }
            }
        }
        fc_worker(smh, fcb, out);

    } else if (bid < 64) {
        // ================= XG: Xg[t] = seq[t] @ Wih^T + bl, 128 cols =================
        __half* Ws = smh;                     // [128][WSTRH_G]
        __half* As = smh + 128 * WSTRH_G;     // [2][128][ASTRH]
        const int n0 = (bid - 32) * 128;

        for (int i = tid; i < 128 * 64; i += NTH) {
            const int r = i >> 6, c = (i & 63) * 8;
            *(uint4*)(Ws + r * WSTRH_G + c) = *(const uint4*)(g_Wihlh + (size_t)(n0 + r) * HH + c);
        }
        __syncthreads();

        for (int t = 1; t < TSTEPS; ++t) {
            wait_ge(g_bar_gru, 32u * (unsigned)t);
            const __half* Abh = g_seqh + (size_t)t * BB * HH;

            float4 acc[4];
#pragma unroll
            for (int ni = 0; ni < 4; ni++) acc[ni] = make_float4(0.f, 0.f, 0.f, 0.f);

            uint4 pr[1];
            a_load(Abh, HH, 0, tid, pr);
            a_store(As, tid, pr);
            __syncthreads();
            for (int kt = 0; kt < 8; ++kt) {
                const int  cur  = kt & 1;
                const bool more = (kt + 1 < 8);
                if (more) a_load(Abh, HH, (kt + 1) * PBK, tid, pr);
                do_kk4<4>(As + cur * BM * ASTRH, Ws, WSTRH_G, kt * PBK, lane, wm, wn, acc);
                if (more) a_store(As + ((kt + 1) & 1) * BM * ASTRH, tid, pr);
                __syncthreads();
            }

#pragma unroll
            for (int ni = 0; ni < 4; ni++) {
                const int r   = wm * 16 + (lane >> 2);
                const int col = n0 + wn * 32 + ni * 8 + 2 * (lane & 3);
                const float b0 = g_bl[col], b1 = g_bl[col + 1];
                float* o0 = g_Xg + ((size_t)t * BB + r) * 4096 + col;
                float* o1 = g_Xg + ((size_t)t * BB + r + 8) * 4096 + col;
                *(float2*)o0 = make_float2(acc[ni].x + b0, acc[ni].y + b1);
                *(float2*)o1 = make_float2(acc[ni].z + b0, acc[ni].w + b1);
            }
            bar_arrive(g_bar_xg);
        }
        fc_worker(smh, fcb, out);

    } else if (bid < 128) {
        // ================= LSTM chain: 64 cols (16 units) =================
        __half* Ws = smh;                     // [64][WSTRH_L]
        __half* As = smh + 64 * WSTRH_L;      // [2][128][ASTRH]
        float*  Cs = (float*)As;              // staging, stride CSTR
        const int n0 = (bid - 64) * 64;

        for (int i = tid; i < 64 * 128; i += NTH) {
            const int r = i >> 7, c = (i & 127) * 8;
            *(uint4*)(Ws + r * WSTRH_L + c) = *(const uint4*)(g_Whhlh + (size_t)(n0 + r) * LL + c);
        }
        __syncthreads();

        for (int t = 0; t < TSTEPS; ++t) {
            if (t >= 1)
                wait_ge2(g_bar_xg, 32u * (unsigned)t, g_bar_lstm, 64u * (unsigned)t);

            const __half* Abh = g_hh + (size_t)(t & 1) * BB * LL;
            __half* hoh       = g_hh + (size_t)((t + 1) & 1) * BB * LL;

            // prefetch Xg[t] and c before the mainloop
            float4 xg[2];
            float  cc[2];
#pragma unroll
            for (int s = 0; s < 2; s++) {
                const int it  = tid + s * NTH;
                const int row = it >> 4;
                const int u   = it & 15;
                xg[s] = *(const float4*)(g_Xg + ((size_t)t * BB + row) * 4096 + n0 + 4 * u);
                cc[s] = g_c[row * LL + (n0 >> 2) + u];
            }

            float4 acc[2];
#pragma unroll
            for (int ni = 0; ni < 2; ni++) acc[ni] = make_float4(0.f, 0.f, 0.f, 0.f);

            if (t >= 1) {   // t == 0: h = 0 -> matmul contributes nothing
                uint4 pr[1];
                a_load(Abh, LL, 0, tid, pr);
                a_store(As, tid, pr);
                __syncthreads();
                for (int kt = 0; kt < 16; ++kt) {
                    const int  cur  = kt & 1;
                    const bool more = (kt + 1 < 16);
                    if (more) a_load(Abh, LL, (kt + 1) * PBK, tid, pr);
                    do_kk4<2>(As + cur * BM * ASTRH, Ws, WSTRH_L, kt * PBK, lane, wm, wn, acc);
                    if (more) a_store(As + ((kt + 1) & 1) * BM * ASTRH, tid, pr);
                    __syncthreads();
                }
            }

#pragma unroll
            for (int ni = 0; ni < 2; ni++) {
                const int r = wm * 16 + (lane >> 2);
                const int c = wn * 16 + ni * 8 + 2 * (lane & 3);
                Cs[r * CSTR + c]           = acc[ni].x;
                Cs[r * CSTR + c + 1]       = acc[ni].y;
                Cs[(r + 8) * CSTR + c]     = acc[ni].z;
                Cs[(r + 8) * CSTR + c + 1] = acc[ni].w;
            }
            __syncthreads();

#pragma unroll
            for (int s = 0; s < 2; s++) {
                const int it  = tid + s * NTH;
                const int u   = it & 15;
                const int row = it >> 4;
                const int jg  = (n0 >> 2) + u;
                const float4 cv = *(const float4*)(Cs + row * CSTR + 4 * u);
                const float ig = sigf(cv.x + xg[s].x);
                const float fg = sigf(cv.y + xg[s].y);
                const float gg = tanhf(cv.z + xg[s].z);
                const float og = sigf(cv.w + xg[s].w);
                const int ci = row * LL + jg;
                const float cn = fg * cc[s] + ig * gg;
                g_c[ci] = cn;
                const float hn = og * tanhf(cn);
                hoh[ci] = __float2half_rn(hn);
                g_hsh[((size_t)t * BB + row) * LL + jg] = __float2half_rn(hn);
            }

            bar_arrive(g_bar_lstm);
        }
        fc_worker(smh, fcb, out);

    } else {
        fc_worker(smh, fcb, out);
    }
}

// ---------------- prep kernels ----------------
__global__ void prep_gru(const float* __restrict__ Wih, const float* __restrict__ Whh,
                         const float* __restrict__ bih, const float* __restrict__ bhh) {
    const int idx = blockIdx.x * blockDim.x + threadIdx.x;
    if (idx < 2048 * 512) {
        const int row = idx >> 9, k = idx & 511;
        const int j = row >> 2, g = row & 3;
        float wg, w1;
        if (g == 0)      { wg = Wih[j * 512 + k] + Whh[j * 512 + k];                 w1 = Whh[j * 512 + k]; }
        else if (g == 1) { wg = Wih[(512 + j) * 512 + k] + Whh[(512 + j) * 512 + k]; w1 = Whh[(512 + j) * 512 + k]; }
        else if (g == 2) { wg = Wih[(1024 + j) * 512 + k];                           w1 = 0.f; }
        else             { wg = Whh[(1024 + j) * 512 + k];                           w1 = wg; }
        g_Wgh[idx]  = __float2half_rn(wg);
        g_Wg1h[idx] = __float2half_rn(w1);
    }
    if (idx < 2048) {
        const int j = idx >> 2, g = idx & 3;
        float b;
        if (g == 0)      b = bih[j] + bhh[j];
        else if (g == 1) b = bih[512 + j] + bhh[512 + j];
        else if (g == 2) b = bih[1024 + j];
        else             b = bhh[1024 + j];
        g_bg[idx] = b;
    }
}

__global__ void prep_lstm(const float* __restrict__ Wih, const float* __restrict__ Whh,
                          const float* __restrict__ bih, const float* __restrict__ bhh,
                          const float* __restrict__ fcW) {
    const int idx = blockIdx.x * blockDim.x + threadIdx.x;
    if (idx < 4096 * 1024) {
        const int row = idx >> 10, k = idx & 1023;
        const int j = row >> 2, p = row & 3;
        g_Whhlh[idx] = __float2half_rn(Whh[(size_t)(p * 1024 + j) * 1024 + k]);
    }
    if (idx < 4096 * 512) {
        const int row = idx >> 9, k = idx & 511;
        const int j = row >> 2, p = row & 3;
        g_Wihlh[idx] = __float2half_rn(Wih[(size_t)(p * 1024 + j) * 512 + k]);
    }
    if (idx < 1024 * 1024) {
        g_fcWh[idx] = __float2half_rn(fcW[idx]);
    }
    if (idx < 4096) {
        const int j = idx >> 2, p = idx & 3;
        g_bl[idx] = bih[p * 1024 + j] + bhh[p * 1024 + j];
    }
}

// zero states, half(z), Xg[0] = bl (seq[0] == 0), reset barriers
__global__ void prep_zero(const float* __restrict__ z) {
    const int idx = blockIdx.x * blockDim.x + threadIdx.x;
    if (idx < BB * LL) { g_hh[idx] = __float2half_rn(0.f); g_c[idx] = 0.f; }
    if (idx < BB * HH) { g_zh[idx] = __float2half_rn(z[idx]); }
    if (idx < BB * 4096) { g_Xg[idx] = g_bl[idx & 4095]; }
    if (idx == 0) { g_bar_gru[0] = 0u; g_bar_xg[0] = 0u; g_bar_lstm[0] = 0u; g_fc_cnt[0] = 0u; }
}

// ---------------- host launcher ----------------
extern "C" void kernel_launch(void* const* d_in, const int* in_sizes, int n_in,
                              void* d_out, int out_size) {
    const float* z    = (const float*)d_in[0];
    const float* gWih = (const float*)d_in[2];
    const float* gWhh = (const float*)d_in[3];
    const float* gbih = (const float*)d_in[4];
    const float* gbhh = (const float*)d_in[5];
    const float* lWih = (const float*)d_in[6];
    const float* lWhh = (const float*)d_in[7];
    const float* lbih = (const float*)d_in[8];
    const float* lbhh = (const float*)d_in[9];
    const float* fcW  = (const float*)d_in[10];
    const float* fcb  = (const float*)d_in[11];
    float* out = (float*)d_out;

    cudaFuncSetAttribute(fused_persist, cudaFuncAttributeMaxDynamicSharedMemorySize, SMEM_FUSED);

    prep_gru <<<(2048 * 512 + 255) / 256, 256>>>(gWih, gWhh, gbih, gbhh);
    prep_lstm<<<(4096 * 1024 + 255) / 256, 256>>>(lWih, lWhh, lbih, lbhh, fcW);
    prep_zero<<<(BB * 4096 + 255) / 256, 256>>>(z);

    // one fused persistent kernel: GRU | XG | LSTM | FC pipelined on disjoint
    // CTA sets (32 + 32 + 64 + 20 = 148), 1024 threads/CTA (32 warps/SM)
    fused_persist<<<148, NTH, SMEM_FUSED>>>(z, fcb, out);
}

// round 10
// speedup vs baseline: 1.3339x; 1.3339x over previous
#include <cuda_runtime.h>
#include <cuda_fp16.h>
#include <cstdint>
#include <cstddef>

// ---------------- problem constants ----------------
#define TSTEPS 256
#define BB 128      // batch
#define HH 512      // GRU hidden
#define LL 1024     // LSTM hidden
#define VV 1024     // vocab

// ---------------- config (R8 base: 512 thr, 4x4 warp grid) ----------------
#define NTH 512
#define BM 128
#define PBK 64
#define ASTRH (PBK + 8)             // 72 halfs (row stride 144B: ldmatrix conflict-free)
#define WSTRH_G (HH + 8)            // 520 halfs (1040B)
#define WSTRH_L (LL + 8)            // 1032 halfs (2064B)
#define CSTR 68                     // fp32 staging stride

#define SMEM_FUSED 169984
#define F_ATILE (2 * 64 * ASTRH)    // FC As offset (halfs)

// ---------------- persistent device scratch ----------------
__device__ __align__(256) __half g_Wgh  [2048 * 512];
__device__ __align__(256) __half g_Wg1h [2048 * 512];
__device__ __align__(256) float  g_bg   [2048];
__device__ __align__(256) __half g_Wihlh[4096 * 512];
__device__ __align__(256) float  g_bl   [4096];
__device__ __align__(256) __half g_Whhlh[4096 * 1024];
__device__ __align__(256) __half g_fcWh [1024 * 1024];
__device__ __align__(256) float  g_x    [2 * BB * HH];
__device__ __align__(256) __half g_xh   [2 * BB * HH];
__device__ __align__(256) __half g_zh   [BB * HH];
__device__ __align__(256) __half g_seqh [TSTEPS * BB * HH];
__device__ __align__(256) float  g_Xg   [(size_t)TSTEPS * BB * 4096];
__device__ __align__(256) __half g_hh   [2 * BB * LL];
__device__ __align__(256) float  g_c    [BB * LL];
__device__ __align__(256) __half g_hsh  [(size_t)TSTEPS * BB * LL];
__device__ __align__(128) unsigned g_bar_gru[32];
__device__ __align__(128) unsigned g_bar_xg[32];
__device__ __align__(128) unsigned g_bar_lstm[32];
__device__ __align__(128) unsigned g_fc_cnt[32];

// ---------------- helpers ----------------
__device__ __forceinline__ void mma_f16(float4& d,
                                        uint32_t a0, uint32_t a1, uint32_t a2, uint32_t a3,
                                        uint32_t b0, uint32_t b1) {
    asm volatile(
        "mma.sync.aligned.m16n8k16.row.col.f32.f16.f16.f32 "
        "{%0,%1,%2,%3}, {%4,%5,%6,%7}, {%8,%9}, {%0,%1,%2,%3};\n"
        : "+f"(d.x), "+f"(d.y), "+f"(d.z), "+f"(d.w)
        : "r"(a0), "r"(a1), "r"(a2), "r"(a3), "r"(b0), "r"(b1));
}

__device__ __forceinline__ void ldsm_x4(uint32_t& r0, uint32_t& r1, uint32_t& r2, uint32_t& r3,
                                        uint32_t addr) {
    asm volatile("ldmatrix.sync.aligned.m8n8.x4.shared.b16 {%0,%1,%2,%3}, [%4];"
                 : "=r"(r0), "=r"(r1), "=r"(r2), "=r"(r3) : "r"(addr));
}
__device__ __forceinline__ void ldsm_x2(uint32_t& r0, uint32_t& r1, uint32_t addr) {
    asm volatile("ldmatrix.sync.aligned.m8n8.x2.shared.b16 {%0,%1}, [%2];"
                 : "=r"(r0), "=r"(r1) : "r"(addr));
}

__device__ __forceinline__ float sigf(float x) { return 1.0f / (1.0f + expf(-x)); }

__device__ __forceinline__ void bar_arrive(unsigned* bar) {
    __syncthreads();
    if (threadIdx.x == 0)
        asm volatile("red.release.gpu.global.add.u32 [%0], 1;" :: "l"(bar) : "memory");
}
__device__ __forceinline__ void wait_ge(unsigned* bar, unsigned target) {
    if (threadIdx.x == 0) {
        unsigned v;
        do {
            asm volatile("ld.acquire.gpu.global.b32 %0, [%1];" : "=r"(v) : "l"(bar));
        } while (v < target);
    }
    __syncthreads();
}
__device__ __forceinline__ void wait_ge2(unsigned* barA, unsigned tA,
                                         unsigned* barB, unsigned tB) {
    if (threadIdx.x == 0) {
        unsigned va, vb;
        do {
            asm volatile("ld.acquire.gpu.global.b32 %0, [%1];" : "=r"(va) : "l"(barA));
            asm volatile("ld.acquire.gpu.global.b32 %0, [%1];" : "=r"(vb) : "l"(barB));
        } while (va < tA || vb < tB);
    }
    __syncthreads();
}

// lane offsets (bytes) for ldmatrix source addresses
__device__ __forceinline__ uint32_t a_lane_off(int lane) {
    const int am = lane >> 3;                          // matrix index 0..3
    return (uint32_t)((((am & 1) * 8 + (lane & 7)) * ASTRH) * 2 + (am >> 1) * 16);
}
__device__ __forceinline__ uint32_t b_lane_off(int lane, int wstr) {
    return (uint32_t)(((lane & 7) * wstr) * 2 + ((lane >> 3) & 1) * 16);
}

// A-tile [128][64 halfs] loaders (R8-proven): 8 threads/row, 2 rows per thread
__device__ __forceinline__ void a_load(const __half* __restrict__ A, int ldK, int k0,
                                       int tid, uint4* pr) {
    const int rL = tid >> 3, ch = (tid & 7) * 8;
#pragma unroll
    for (int i = 0; i < 2; i++)
        pr[i] = *(const uint4*)(A + (size_t)(rL + 64 * i) * ldK + k0 + ch);
}
__device__ __forceinline__ void a_store(__half* buf, int tid, const uint4* pr) {
    const int rL = tid >> 3, ch = (tid & 7) * 8;
#pragma unroll
    for (int i = 0; i < 2; i++)
        *(uint4*)(buf + (rL + 64 * i) * ASTRH + ch) = pr[i];
}

// one PBK=64 k-slab via ldmatrix. AcB: byte addr of A tile buf; WsB: byte addr of
// weight rows at this kt's k offset; wstr in halfs. Warp 4x4: wm*32 rows, wn*(NI*8) cols.
template <int NI>
__device__ __forceinline__ void do_kk4(uint32_t AcB, uint32_t WsB, int wstr,
                                       uint32_t alo, uint32_t blo,
                                       int wm, int wn, float4 (&acc)[2][NI]) {
#pragma unroll
    for (int kk = 0; kk < 4; kk++) {
        uint32_t af[2][4];
#pragma unroll
        for (int mi = 0; mi < 2; mi++) {
            const uint32_t aaddr = AcB + (uint32_t)(((wm * 32 + mi * 16) * ASTRH + kk * 16) * 2) + alo;
            ldsm_x4(af[mi][0], af[mi][1], af[mi][2], af[mi][3], aaddr);
        }
#pragma unroll
        for (int ni = 0; ni < NI; ni++) {
            const uint32_t baddr = WsB + (uint32_t)(((wn * (NI * 8) + ni * 8) * wstr + kk * 16) * 2) + blo;
            uint32_t b0, b1;
            ldsm_x2(b0, b1, baddr);
#pragma unroll
            for (int mi = 0; mi < 2; mi++)
                mma_f16(acc[mi][ni], af[mi][0], af[mi][1], af[mi][2], af[mi][3], b0, b1);
        }
    }
}

// ============================================================================
// FC work-steal: logits tile [128 x 64] = hs_t @ fcW^T + fcb
// ============================================================================
__device__ void fc_worker(__half* smh, uint32_t smb, const float* __restrict__ fcb,
                          float* __restrict__ out) {
    __shared__ int s_tile;
    __half* Bs = smh;               // [2][64][ASTRH]
    __half* As = smh + F_ATILE;     // [2][128][ASTRH]
    const uint32_t bs_u32 = smb;
    const uint32_t as_u32 = smb + F_ATILE * 2;

    const int tid  = threadIdx.x;
    const int lane = tid & 31;
    const int wid  = tid >> 5;
    const int wm   = wid & 3;
    const int wn   = wid >> 2;
    const uint32_t alo = a_lane_off(lane);
    const uint32_t blo = b_lane_off(lane, ASTRH);

    while (true) {
        __syncthreads();
        if (tid == 0) s_tile = (int)atomicAdd(&g_fc_cnt[0], 1u);
        __syncthreads();
        const int tile = s_tile;
        if (tile >= TSTEPS * 16) return;
        const int t  = tile >> 4;
        const int n0 = (tile & 15) * 64;
        wait_ge(g_bar_lstm, 64u * (unsigned)(t + 1));

        const __half* Abh = g_hsh  + (size_t)t * BB * LL;
        const __half* Wb  = g_fcWh + (size_t)n0 * LL;

        float4 acc[2][2];
#pragma unroll
        for (int mi = 0; mi < 2; mi++)
#pragma unroll
            for (int ni = 0; ni < 2; ni++) acc[mi][ni] = make_float4(0.f, 0.f, 0.f, 0.f);

        uint4 pr[2], qr;
        a_load(Abh, LL, 0, tid, pr);
        {
            const int r = tid >> 3, cb = (tid & 7) * 8;
            qr = *(const uint4*)(Wb + (size_t)r * LL + cb);
        }
        a_store(As, tid, pr);
        {
            const int r = tid >> 3, cb = (tid & 7) * 8;
            *(uint4*)(Bs + r * ASTRH + cb) = qr;
        }
        __syncthreads();

        for (int kt = 0; kt < 16; ++kt) {
            const int  cur  = kt & 1;
            const bool more = (kt + 1 < 16);
            if (more) {
                const int k0 = (kt + 1) * PBK;
                a_load(Abh, LL, k0, tid, pr);
                const int r = tid >> 3, cb = (tid & 7) * 8;
                qr = *(const uint4*)(Wb + (size_t)r * LL + k0 + cb);
            }
            do_kk4<2>(as_u32 + cur * BM * ASTRH * 2,
                      bs_u32 + cur * 64 * ASTRH * 2, ASTRH,
                      alo, blo, wm, wn, acc);
            if (more) {
                const int nxt = cur ^ 1;
                a_store(As + nxt * BM * ASTRH, tid, pr);
                const int r = tid >> 3, cb = (tid & 7) * 8;
                *(uint4*)(Bs + nxt * 64 * ASTRH + r * ASTRH + cb) = qr;
            }
            __syncthreads();
        }

#pragma unroll
        for (int mi = 0; mi < 2; mi++) {
#pragma unroll
            for (int ni = 0; ni < 2; ni++) {
                const int r   = wm * 32 + mi * 16 + (lane >> 2);
                const int col = n0 + wn * 16 + ni * 8 + 2 * (lane & 3);
                const float b0 = fcb[col], b1 = fcb[col + 1];
                float* o0 = out + ((size_t)r * TSTEPS + t) * VV + col;
                float* o1 = out + ((size_t)(r + 8) * TSTEPS + t) * VV + col;
                *(float2*)o0 = make_float2(acc[mi][ni].x + b0, acc[mi][ni].y + b1);
                *(float2*)o1 = make_float2(acc[mi][ni].z + b0, acc[mi][ni].w + b1);
            }
        }
    }
}

// ============================================================================
// Fused pipelined kernel, grid = 148 (all co-resident, 512 thr = 16 warps/SM):
//   bid 0-31:    GRU chain, 64 cols each
//   bid 32-63:   XG, 128 cols each (one step behind GRU)
//   bid 64-127:  LSTM chain, 64 cols each (consumes Xg[t])
//   bid 128-147: FC work-steal (chain CTAs join at the end)
// ============================================================================
__global__ void __launch_bounds__(NTH)
fused_persist(const float* __restrict__ z, const float* __restrict__ fcb,
              float* __restrict__ out) {
    extern __shared__ __half smh[];
    const uint32_t smb = (uint32_t)__cvta_generic_to_shared(smh);
    const int tid  = threadIdx.x;
    const int lane = tid & 31;
    const int wid  = tid >> 5;
    const int wm   = wid & 3;
    const int wn   = wid >> 2;
    const int bid  = blockIdx.x;
    const uint32_t alo = a_lane_off(lane);

    if (bid < 32) {
        // ================= GRU chain: 64 cols (16 units) =================
        __half* Ws = smh;                     // [64][WSTRH_G]
        __half* As = smh + 64 * WSTRH_G;      // [2][128][ASTRH]
        float*  Cs = (float*)As;              // staging, stride CSTR
        const uint32_t ws_u32 = smb;
        const uint32_t as_u32 = smb + 64 * WSTRH_G * 2;
        const uint32_t blo = b_lane_off(lane, WSTRH_G);
        const int n0 = bid * 64;

        for (int i = tid; i < 64 * 64; i += NTH) {
            const int r = i >> 6, c = (i & 63) * 8;
            *(uint4*)(Ws + r * WSTRH_G + c) = *(const uint4*)(g_Wg1h + (size_t)(n0 + r) * HH + c);
        }
        __syncthreads();

        for (int t = 1; t < TSTEPS; ++t) {
            const __half* Abh  = (t == 1) ? g_zh : g_xh + (size_t)((t - 1) & 1) * BB * HH;
            const float*  hp32 = (t == 1) ? z    : g_x  + (size_t)((t - 1) & 1) * BB * HH;
            float*  xo32 = g_x    + (size_t)(t & 1) * BB * HH;
            __half* xoh  = g_xh   + (size_t)(t & 1) * BB * HH;
            __half* so   = g_seqh + (size_t)t * BB * HH;

            float hp[4];
#pragma unroll
            for (int s = 0; s < 4; s++) {
                const int it = tid + s * NTH;
                hp[s] = hp32[(size_t)(it >> 4) * HH + (n0 >> 2) + (it & 15)];
            }

            float4 acc[2][2];
#pragma unroll
            for (int mi = 0; mi < 2; mi++)
#pragma unroll
                for (int ni = 0; ni < 2; ni++) acc[mi][ni] = make_float4(0.f, 0.f, 0.f, 0.f);

            uint4 pr[2];
            a_load(Abh, HH, 0, tid, pr);
            a_store(As, tid, pr);
            __syncthreads();
            for (int kt = 0; kt < 8; ++kt) {
                const int  cur  = kt & 1;
                const bool more = (kt + 1 < 8);
                if (more) a_load(Abh, HH, (kt + 1) * PBK, tid, pr);
                do_kk4<2>(as_u32 + cur * BM * ASTRH * 2,
                          ws_u32 + kt * PBK * 2, WSTRH_G,
                          alo, blo, wm, wn, acc);
                if (more) a_store(As + ((kt + 1) & 1) * BM * ASTRH, tid, pr);
                __syncthreads();
            }

#pragma unroll
            for (int mi = 0; mi < 2; mi++) {
#pragma unroll
                for (int ni = 0; ni < 2; ni++) {
                    const int r = wm * 32 + mi * 16 + (lane >> 2);
                    const int c = wn * 16 + ni * 8 + 2 * (lane & 3);
                    const float b0 = g_bg[n0 + c], b1 = g_bg[n0 + c + 1];
                    Cs[r * CSTR + c]           = acc[mi][ni].x + b0;
                    Cs[r * CSTR + c + 1]       = acc[mi][ni].y + b1;
                    Cs[(r + 8) * CSTR + c]     = acc[mi][ni].z + b0;
                    Cs[(r + 8) * CSTR + c + 1] = acc[mi][ni].w + b1;
                }
            }
            __syncthreads();

#pragma unroll
            for (int s = 0; s < 4; s++) {
                const int it  = tid + s * NTH;
                const int u   = it & 15;
                const int row = it >> 4;
                const int jg  = (n0 >> 2) + u;
                const float4 cv = *(const float4*)(Cs + row * CSTR + 4 * u);
                const float rg = sigf(cv.x);
                const float zg = sigf(cv.y);
                const float nn = tanhf(cv.z + rg * cv.w);
                const float xn = (1.f - zg) * nn + zg * hp[s];
                const int oi = row * HH + jg;
                xo32[oi] = xn;
                xoh[oi]  = __float2half_rn(xn);
                so[oi]   = __float2half_rn(fmaxf(xn, 0.f));
            }

            bar_arrive(g_bar_gru);
            if (t < TSTEPS - 1) {
                wait_ge(g_bar_gru, 32u * (unsigned)t);
                if (t == 1) {   // swap to combined weights for t >= 2
                    for (int i = tid; i < 64 * 64; i += NTH) {
                        const int r = i >> 6, c = (i & 63) * 8;
                        *(uint4*)(Ws + r * WSTRH_G + c) =
                            *(const uint4*)(g_Wgh + (size_t)(n0 + r) * HH + c);
                    }
                    __syncthreads();
                }
            }
        }
        fc_worker(smh, smb, fcb, out);

    } else if (bid < 64) {
        // ================= XG: Xg[t] = seq[t] @ Wih^T + bl, 128 cols =================
        __half* Ws = smh;                     // [128][WSTRH_G]
        __half* As = smh + 128 * WSTRH_G;     // [2][128][ASTRH]
        const uint32_t ws_u32 = smb;
        const uint32_t as_u32 = smb + 128 * WSTRH_G * 2;
        const uint32_t blo = b_lane_off(lane, WSTRH_G);
        const int n0 = (bid - 32) * 128;

        for (int i = tid; i < 128 * 64; i += NTH) {
            const int r = i >> 6, c = (i & 63) * 8;
            *(uint4*)(Ws + r * WSTRH_G + c) = *(const uint4*)(g_Wihlh + (size_t)(n0 + r) * HH + c);
        }
        __syncthreads();

        for (int t = 1; t < TSTEPS; ++t) {
            wait_ge(g_bar_gru, 32u * (unsigned)t);
            const __half* Abh = g_seqh + (size_t)t * BB * HH;

            float4 acc[2][4];
#pragma unroll
            for (int mi = 0; mi < 2; mi++)
#pragma unroll
                for (int ni = 0; ni < 4; ni++) acc[mi][ni] = make_float4(0.f, 0.f, 0.f, 0.f);

            uint4 pr[2];
            a_load(Abh, HH, 0, tid, pr);
            a_store(As, tid, pr);
            __syncthreads();
            for (int kt = 0; kt < 8; ++kt) {
                const int  cur  = kt & 1;
                const bool more = (kt + 1 < 8);
                if (more) a_load(Abh, HH, (kt + 1) * PBK, tid, pr);
                do_kk4<4>(as_u32 + cur * BM * ASTRH * 2,
                          ws_u32 + kt * PBK * 2, WSTRH_G,
                          alo, blo, wm, wn, acc);
                if (more) a_store(As + ((kt + 1) & 1) * BM * ASTRH, tid, pr);
                __syncthreads();
            }

#pragma unroll
            for (int mi = 0; mi < 2; mi++) {
#pragma unroll
                for (int ni = 0; ni < 4; ni++) {
                    const int r   = wm * 32 + mi * 16 + (lane >> 2);
                    const int col = n0 + wn * 32 + ni * 8 + 2 * (lane & 3);
                    const float b0 = g_bl[col], b1 = g_bl[col + 1];
                    float* o0 = g_Xg + ((size_t)t * BB + r) * 4096 + col;
                    float* o1 = g_Xg + ((size_t)t * BB + r + 8) * 4096 + col;
                    *(float2*)o0 = make_float2(acc[mi][ni].x + b0, acc[mi][ni].y + b1);
                    *(float2*)o1 = make_float2(acc[mi][ni].z + b0, acc[mi][ni].w + b1);
                }
            }
            bar_arrive(g_bar_xg);
        }
        fc_worker(smh, smb, fcb, out);

    } else if (bid < 128) {
        // ================= LSTM chain: 64 cols (16 units) =================
        __half* Ws = smh;                     // [64][WSTRH_L]
        __half* As = smh + 64 * WSTRH_L;      // [2][128][ASTRH]
        float*  Cs = (float*)As;              // staging, stride CSTR
        const uint32_t ws_u32 = smb;
        const uint32_t as_u32 = smb + 64 * WSTRH_L * 2;
        const uint32_t blo = b_lane_off(lane, WSTRH_L);
        const int n0 = (bid - 64) * 64;

        for (int i = tid; i < 64 * 128; i += NTH) {
            const int r = i >> 7, c = (i & 127) * 8;
            *(uint4*)(Ws + r * WSTRH_L + c) = *(const uint4*)(g_Whhlh + (size_t)(n0 + r) * LL + c);
        }
        __syncthreads();

        for (int t = 0; t < TSTEPS; ++t) {
            if (t >= 1)
                wait_ge2(g_bar_xg, 32u * (unsigned)t, g_bar_lstm, 64u * (unsigned)t);

            const __half* Abh = g_hh + (size_t)(t & 1) * BB * LL;
            __half* hoh       = g_hh + (size_t)((t + 1) & 1) * BB * LL;

            // prefetch Xg[t] and c before the mainloop
            float4 xg[4];
            float  cc[4];
#pragma unroll
            for (int s = 0; s < 4; s++) {
                const int it  = tid + s * NTH;
                const int row = it >> 4;
                const int u   = it & 15;
                xg[s] = *(const float4*)(g_Xg + ((size_t)t * BB + row) * 4096 + n0 + 4 * u);
                cc[s] = g_c[row * LL + (n0 >> 2) + u];
            }

            float4 acc[2][2];
#pragma unroll
            for (int mi = 0; mi < 2; mi++)
#pragma unroll
                for (int ni = 0; ni < 2; ni++) acc[mi][ni] = make_float4(0.f, 0.f, 0.f, 0.f);

            if (t >= 1) {   // t == 0: h = 0 -> matmul contributes nothing
                uint4 pr[2];
                a_load(Abh, LL, 0, tid, pr);
                a_store(As, tid, pr);
                __syncthreads();
                for (int kt = 0; kt < 16; ++kt) {
                    const int  cur  = kt & 1;
                    const bool more = (kt + 1 < 16);
                    if (more) a_load(Abh, LL, (kt + 1) * PBK, tid, pr);
                    do_kk4<2>(as_u32 + cur * BM * ASTRH * 2,
                              ws_u32 + kt * PBK * 2, WSTRH_L,
                              alo, blo, wm, wn, acc);
                    if (more) a_store(As + ((kt + 1) & 1) * BM * ASTRH, tid, pr);
                    __syncthreads();
                }
            }

#pragma unroll
            for (int mi = 0; mi < 2; mi++) {
#pragma unroll
                for (int ni = 0; ni < 2; ni++) {
                    const int r = wm * 32 + mi * 16 + (lane >> 2);
                    const int c = wn * 16 + ni * 8 + 2 * (lane & 3);
                    Cs[r * CSTR + c]           = acc[mi][ni].x;
                    Cs[r * CSTR + c + 1]       = acc[mi][ni].y;
                    Cs[(r + 8) * CSTR + c]     = acc[mi][ni].z;
                    Cs[(r + 8) * CSTR + c + 1] = acc[mi][ni].w;
                }
            }
            __syncthreads();

#pragma unroll
            for (int s = 0; s < 4; s++) {
                const int it  = tid + s * NTH;
                const int u   = it & 15;
                const int row = it >> 4;
                const int jg  = (n0 >> 2) + u;
                const float4 cv = *(const float4*)(Cs + row * CSTR + 4 * u);
                const float ig = sigf(cv.x + xg[s].x);
                const float fg = sigf(cv.y + xg[s].y);
                const float gg = tanhf(cv.z + xg[s].z);
                const float og = sigf(cv.w + xg[s].w);
                const int ci = row * LL + jg;
                const float cn = fg * cc[s] + ig * gg;
                g_c[ci] = cn;
                const float hn = og * tanhf(cn);
                hoh[ci] = __float2half_rn(hn);
                g_hsh[((size_t)t * BB + row) * LL + jg] = __float2half_rn(hn);
            }

            bar_arrive(g_bar_lstm);
        }
        fc_worker(smh, smb, fcb, out);

    } else {
        fc_worker(smh, smb, fcb, out);
    }
}

// ---------------- prep kernels ----------------
__global__ void prep_gru(const float* __restrict__ Wih, const float* __restrict__ Whh,
                         const float* __restrict__ bih, const float* __restrict__ bhh) {
    const int idx = blockIdx.x * blockDim.x + threadIdx.x;
    if (idx < 2048 * 512) {
        const int row = idx >> 9, k = idx & 511;
        const int j = row >> 2, g = row & 3;
        float wg, w1;
        if (g == 0)      { wg = Wih[j * 512 + k] + Whh[j * 512 + k];                 w1 = Whh[j * 512 + k]; }
        else if (g == 1) { wg = Wih[(512 + j) * 512 + k] + Whh[(512 + j) * 512 + k]; w1 = Whh[(512 + j) * 512 + k]; }
        else if (g == 2) { wg = Wih[(1024 + j) * 512 + k];                           w1 = 0.f; }
        else             { wg = Whh[(1024 + j) * 512 + k];                           w1 = wg; }
        g_Wgh[idx]  = __float2half_rn(wg);
        g_Wg1h[idx] = __float2half_rn(w1);
    }
    if (idx < 2048) {
        const int j = idx >> 2, g = idx & 3;
        float b;
        if (g == 0)      b = bih[j] + bhh[j];
        else if (g == 1) b = bih[512 + j] + bhh[512 + j];
        else if (g == 2) b = bih[1024 + j];
        else             b = bhh[1024 + j];
        g_bg[idx] = b;
    }
}

__global__ void prep_lstm(const float* __restrict__ Wih, const float* __restrict__ Whh,
                          const float* __restrict__ bih, const float* __restrict__ bhh,
                          const float* __restrict__ fcW) {
    const int idx = blockIdx.x * blockDim.x + threadIdx.x;
    if (idx < 4096 * 1024) {
        const int row = idx >> 10, k = idx & 1023;
        const int j = row >> 2, p = row & 3;
        g_Whhlh[idx] = __float2half_rn(Whh[(size_t)(p * 1024 + j) * 1024 + k]);
    }
    if (idx < 4096 * 512) {
        const int row = idx >> 9, k = idx & 511;
        const int j = row >> 2, p = row & 3;
        g_Wihlh[idx] = __float2half_rn(Wih[(size_t)(p * 1024 + j) * 512 + k]);
    }
    if (idx < 1024 * 1024) {
        g_fcWh[idx] = __float2half_rn(fcW[idx]);
    }
    if (idx < 4096) {
        const int j = idx >> 2, p = idx & 3;
        g_bl[idx] = bih[p * 1024 + j] + bhh[p * 1024 + j];
    }
}

// zero states, half(z), Xg[0] = bl (seq[0] == 0), reset barriers
__global__ void prep_zero(const float* __restrict__ z) {
    const int idx = blockIdx.x * blockDim.x + threadIdx.x;
    if (idx < BB * LL) { g_hh[idx] = __float2half_rn(0.f); g_c[idx] = 0.f; }
    if (idx < BB * HH) { g_zh[idx] = __float2half_rn(z[idx]); }
    if (idx < BB * 4096) { g_Xg[idx] = g_bl[idx & 4095]; }
    if (idx == 0) { g_bar_gru[0] = 0u; g_bar_xg[0] = 0u; g_bar_lstm[0] = 0u; g_fc_cnt[0] = 0u; }
}

// ---------------- host launcher ----------------
extern "C" void kernel_launch(void* const* d_in, const int* in_sizes, int n_in,
                              void* d_out, int out_size) {
    const float* z    = (const float*)d_in[0];
    const float* gWih = (const float*)d_in[2];
    const float* gWhh = (const float*)d_in[3];
    const float* gbih = (const float*)d_in[4];
    const float* gbhh = (const float*)d_in[5];
    const float* lWih = (const float*)d_in[6];
    const float* lWhh = (const float*)d_in[7];
    const float* lbih = (const float*)d_in[8];
    const float* lbhh = (const float*)d_in[9];
    const float* fcW  = (const float*)d_in[10];
    const float* fcb  = (const float*)d_in[11];
    float* out = (float*)d_out;

    cudaFuncSetAttribute(fused_persist, cudaFuncAttributeMaxDynamicSharedMemorySize, SMEM_FUSED);

    prep_gru <<<(2048 * 512 + 255) / 256, 256>>>(gWih, gWhh, gbih, gbhh);
    prep_lstm<<<(4096 * 1024 + 255) / 256, 256>>>(lWih, lWhh, lbih, lbhh, fcW);
    prep_zero<<<(BB * 4096 + 255) / 256, 256>>>(z);

    // one fused persistent kernel: GRU | XG | LSTM | FC pipelined on disjoint
    // CTA sets (32 + 32 + 64 + 20 = 148), 512 threads/CTA, ldmatrix mainloop
    fused_persist<<<148, NTH, SMEM_FUSED>>>(z, fcb, out);
}

// round 11
// speedup vs baseline: 1.3762x; 1.0318x over previous
#include <cuda_runtime.h>
#include <cuda_fp16.h>
#include <cstdint>
#include <cstddef>

// ---------------- problem constants ----------------
#define TSTEPS 256
#define BB 128      // batch
#define HH 512      // GRU hidden
#define LL 1024     // LSTM hidden
#define VV 1024     // vocab

// ---------------- config (R10 base + 4-deep cp.async ring) ----------------
#define NTH 512
#define BM 128
#define PBK 64
#define ASTRH (PBK + 8)             // 72 halfs (144B row: ldmatrix conflict-free)
#define WSTRH_G (HH + 8)            // 520 halfs
#define WSTRH_L (LL + 8)            // 1032 halfs
#define CSTR 68                     // fp32 staging stride
#define NBUF 4
#define ABUF_B (BM * ASTRH * 2)     // bytes per A buffer (18432)
#define BBUF_B (64 * ASTRH * 2)     // bytes per FC-B buffer (9216)

// dynamic smem (bytes):
//  GRU : 64*WSTRH_G*2  + 4*ABUF_B = 66560 + 73728  = 140288
//  XG  : 128*WSTRH_G*2 + 4*ABUF_B = 133120 + 73728 = 206848
//  LSTM: 64*WSTRH_L*2  + 4*ABUF_B = 132096 + 73728 = 205824
//  FC  : 4*BBUF_B      + 4*ABUF_B = 36864 + 73728  = 110592
#define SMEM_FUSED 206848
#define F_ATILE (NBUF * 64 * ASTRH)  // FC As offset (halfs)

// ---------------- persistent device scratch ----------------
__device__ __align__(256) __half g_Wgh  [2048 * 512];
__device__ __align__(256) __half g_Wg1h [2048 * 512];
__device__ __align__(256) float  g_bg   [2048];
__device__ __align__(256) __half g_Wihlh[4096 * 512];
__device__ __align__(256) float  g_bl   [4096];
__device__ __align__(256) __half g_Whhlh[4096 * 1024];
__device__ __align__(256) __half g_fcWh [1024 * 1024];
__device__ __align__(256) float  g_x    [2 * BB * HH];
__device__ __align__(256) __half g_xh   [2 * BB * HH];
__device__ __align__(256) __half g_zh   [BB * HH];
__device__ __align__(256) __half g_seqh [TSTEPS * BB * HH];
__device__ __align__(256) float  g_Xg   [(size_t)TSTEPS * BB * 4096];
__device__ __align__(256) __half g_hh   [2 * BB * LL];
__device__ __align__(256) float  g_c    [BB * LL];
__device__ __align__(256) __half g_hsh  [(size_t)TSTEPS * BB * LL];
__device__ __align__(128) unsigned g_bar_gru[32];
__device__ __align__(128) unsigned g_bar_xg[32];
__device__ __align__(128) unsigned g_bar_lstm[32];
__device__ __align__(128) unsigned g_fc_cnt[32];

// ---------------- helpers ----------------
__device__ __forceinline__ void mma_f16(float4& d,
                                        uint32_t a0, uint32_t a1, uint32_t a2, uint32_t a3,
                                        uint32_t b0, uint32_t b1) {
    asm volatile(
        "mma.sync.aligned.m16n8k16.row.col.f32.f16.f16.f32 "
        "{%0,%1,%2,%3}, {%4,%5,%6,%7}, {%8,%9}, {%0,%1,%2,%3};\n"
        : "+f"(d.x), "+f"(d.y), "+f"(d.z), "+f"(d.w)
        : "r"(a0), "r"(a1), "r"(a2), "r"(a3), "r"(b0), "r"(b1));
}

__device__ __forceinline__ void ldsm_x4(uint32_t& r0, uint32_t& r1, uint32_t& r2, uint32_t& r3,
                                        uint32_t addr) {
    asm volatile("ldmatrix.sync.aligned.m8n8.x4.shared.b16 {%0,%1,%2,%3}, [%4];"
                 : "=r"(r0), "=r"(r1), "=r"(r2), "=r"(r3) : "r"(addr));
}
__device__ __forceinline__ void ldsm_x2(uint32_t& r0, uint32_t& r1, uint32_t addr) {
    asm volatile("ldmatrix.sync.aligned.m8n8.x2.shared.b16 {%0,%1}, [%2];"
                 : "=r"(r0), "=r"(r1) : "r"(addr));
}

__device__ __forceinline__ void cpa16(uint32_t dst, const __half* src) {
    asm volatile("cp.async.cg.shared.global [%0], [%1], 16;" :: "r"(dst), "l"(src));
}
#define CP_COMMIT() asm volatile("cp.async.commit_group;" ::: "memory")
#define CP_WAIT2()  asm volatile("cp.async.wait_group 2;"  ::: "memory")

__device__ __forceinline__ float sigf(float x) { return 1.0f / (1.0f + expf(-x)); }

__device__ __forceinline__ void bar_arrive(unsigned* bar) {
    __syncthreads();
    if (threadIdx.x == 0)
        asm volatile("red.release.gpu.global.add.u32 [%0], 1;" :: "l"(bar) : "memory");
}
__device__ __forceinline__ void wait_ge(unsigned* bar, unsigned target) {
    if (threadIdx.x == 0) {
        unsigned v;
        do {
            asm volatile("ld.acquire.gpu.global.b32 %0, [%1];" : "=r"(v) : "l"(bar));
        } while (v < target);
    }
    __syncthreads();
}
__device__ __forceinline__ void wait_ge2(unsigned* barA, unsigned tA,
                                         unsigned* barB, unsigned tB) {
    if (threadIdx.x == 0) {
        unsigned va, vb;
        do {
            asm volatile("ld.acquire.gpu.global.b32 %0, [%1];" : "=r"(va) : "l"(barA));
            asm volatile("ld.acquire.gpu.global.b32 %0, [%1];" : "=r"(vb) : "l"(barB));
        } while (va < tA || vb < tB);
    }
    __syncthreads();
}

// lane offsets (bytes) for ldmatrix source addresses
__device__ __forceinline__ uint32_t a_lane_off(int lane) {
    const int am = lane >> 3;
    return (uint32_t)((((am & 1) * 8 + (lane & 7)) * ASTRH) * 2 + (am >> 1) * 16);
}
__device__ __forceinline__ uint32_t b_lane_off(int lane, int wstr) {
    return (uint32_t)(((lane & 7) * wstr) * 2 + ((lane >> 3) & 1) * 16);
}

// issue one A slab (128 rows x 64 halfs) via cp.async: 2 x 16B per thread
__device__ __forceinline__ void a_issue(uint32_t buf_b, const __half* __restrict__ A,
                                        int ldK, int k0, int tid) {
    const int rL = tid >> 3, ch = (tid & 7) * 8;
    cpa16(buf_b + (uint32_t)((rL * ASTRH + ch) * 2),        A + (size_t)rL * ldK + k0 + ch);
    cpa16(buf_b + (uint32_t)(((rL + 64) * ASTRH + ch) * 2), A + (size_t)(rL + 64) * ldK + k0 + ch);
}
// issue one FC B slab (64 rows x 64 halfs): 1 x 16B per thread
__device__ __forceinline__ void b_issue(uint32_t buf_b, const __half* __restrict__ W,
                                        int ldK, int k0, int tid) {
    const int r = tid >> 3, cb = (tid & 7) * 8;
    cpa16(buf_b + (uint32_t)((r * ASTRH + cb) * 2), W + (size_t)r * ldK + k0 + cb);
}

// one PBK=64 k-slab via ldmatrix (R10-proven)
template <int NI>
__device__ __forceinline__ void do_kk4(uint32_t AcB, uint32_t WsB, int wstr,
                                       uint32_t alo, uint32_t blo,
                                       int wm, int wn, float4 (&acc)[2][NI]) {
#pragma unroll
    for (int kk = 0; kk < 4; kk++) {
        uint32_t af[2][4];
#pragma unroll
        for (int mi = 0; mi < 2; mi++) {
            const uint32_t aaddr = AcB + (uint32_t)(((wm * 32 + mi * 16) * ASTRH + kk * 16) * 2) + alo;
            ldsm_x4(af[mi][0], af[mi][1], af[mi][2], af[mi][3], aaddr);
        }
#pragma unroll
        for (int ni = 0; ni < NI; ni++) {
            const uint32_t baddr = WsB + (uint32_t)(((wn * (NI * 8) + ni * 8) * wstr + kk * 16) * 2) + blo;
            uint32_t b0, b1;
            ldsm_x2(b0, b1, baddr);
#pragma unroll
            for (int mi = 0; mi < 2; mi++)
                mma_f16(acc[mi][ni], af[mi][0], af[mi][1], af[mi][2], af[mi][3], b0, b1);
        }
    }
}

// ============================================================================
// FC work-steal: logits tile [128 x 64] = hs_t @ fcW^T + fcb (A+B cp.async ring)
// ============================================================================
__device__ void fc_worker(uint32_t smb, const float* __restrict__ fcb,
                          float* __restrict__ out) {
    __shared__ int s_tile;
    const uint32_t bs_u32 = smb;                    // 4 x [64][ASTRH]
    const uint32_t as_u32 = smb + F_ATILE * 2;      // 4 x [128][ASTRH]

    const int tid  = threadIdx.x;
    const int lane = tid & 31;
    const int wid  = tid >> 5;
    const int wm   = wid & 3;
    const int wn   = wid >> 2;
    const uint32_t alo = a_lane_off(lane);
    const uint32_t blo = b_lane_off(lane, ASTRH);

    while (true) {
        __syncthreads();
        if (tid == 0) s_tile = (int)atomicAdd(&g_fc_cnt[0], 1u);
        __syncthreads();
        const int tile = s_tile;
        if (tile >= TSTEPS * 16) return;
        const int t  = tile >> 4;
        const int n0 = (tile & 15) * 64;
        wait_ge(g_bar_lstm, 64u * (unsigned)(t + 1));

        const __half* Abh = g_hsh  + (size_t)t * BB * LL;
        const __half* Wb  = g_fcWh + (size_t)n0 * LL;

        float4 acc[2][2];
#pragma unroll
        for (int mi = 0; mi < 2; mi++)
#pragma unroll
            for (int ni = 0; ni < 2; ni++) acc[mi][ni] = make_float4(0.f, 0.f, 0.f, 0.f);

#pragma unroll
        for (int s = 0; s < 3; s++) {
            a_issue(as_u32 + s * ABUF_B, Abh, LL, s * PBK, tid);
            b_issue(bs_u32 + s * BBUF_B, Wb,  LL, s * PBK, tid);
            CP_COMMIT();
        }
        for (int kt = 0; kt < 16; ++kt) {
            CP_WAIT2();
            __syncthreads();
            if (kt + 3 < 16) {
                const int b = (kt + 3) & (NBUF - 1);
                a_issue(as_u32 + b * ABUF_B, Abh, LL, (kt + 3) * PBK, tid);
                b_issue(bs_u32 + b * BBUF_B, Wb,  LL, (kt + 3) * PBK, tid);
            }
            CP_COMMIT();
            const int c = kt & (NBUF - 1);
            do_kk4<2>(as_u32 + c * ABUF_B, bs_u32 + c * BBUF_B, ASTRH,
                      alo, blo, wm, wn, acc);
        }

#pragma unroll
        for (int mi = 0; mi < 2; mi++) {
#pragma unroll
            for (int ni = 0; ni < 2; ni++) {
                const int r   = wm * 32 + mi * 16 + (lane >> 2);
                const int col = n0 + wn * 16 + ni * 8 + 2 * (lane & 3);
                const float b0 = fcb[col], b1 = fcb[col + 1];
                float* o0 = out + ((size_t)r * TSTEPS + t) * VV + col;
                float* o1 = out + ((size_t)(r + 8) * TSTEPS + t) * VV + col;
                *(float2*)o0 = make_float2(acc[mi][ni].x + b0, acc[mi][ni].y + b1);
                *(float2*)o1 = make_float2(acc[mi][ni].z + b0, acc[mi][ni].w + b1);
            }
        }
    }
}

// generic chain mainloop: NK slabs of A (128 x PBK) against resident weights
template <int NI>
__device__ __forceinline__ void chain_mainloop(int NK, const __half* __restrict__ Abh,
                                               int ldK, uint32_t as_u32, uint32_t ws_u32,
                                               int wstr, uint32_t alo, uint32_t blo,
                                               int wm, int wn, int tid,
                                               float4 (&acc)[2][NI]) {
#pragma unroll
    for (int s = 0; s < 3; s++) {
        if (s < NK) a_issue(as_u32 + s * ABUF_B, Abh, ldK, s * PBK, tid);
        CP_COMMIT();
    }
    for (int kt = 0; kt < NK; ++kt) {
        CP_WAIT2();
        __syncthreads();
        if (kt + 3 < NK)
            a_issue(as_u32 + ((kt + 3) & (NBUF - 1)) * ABUF_B, Abh, ldK, (kt + 3) * PBK, tid);
        CP_COMMIT();
        do_kk4<NI>(as_u32 + (kt & (NBUF - 1)) * ABUF_B, ws_u32 + kt * PBK * 2, wstr,
                   alo, blo, wm, wn, acc);
    }
    __syncthreads();   // protect As reuse as Cs staging
}

// ============================================================================
// Fused pipelined kernel, grid = 148 (512 thr = 16 warps/SM):
//   bid 0-31: GRU (64 cols) | bid 32-63: XG (128 cols) | bid 64-127: LSTM (64 cols)
//   bid 128-147: FC steal (chain CTAs join at the end)
// ============================================================================
__global__ void __launch_bounds__(NTH)
fused_persist(const float* __restrict__ z, const float* __restrict__ fcb,
              float* __restrict__ out) {
    extern __shared__ __half smh[];
    const uint32_t smb = (uint32_t)__cvta_generic_to_shared(smh);
    const int tid  = threadIdx.x;
    const int lane = tid & 31;
    const int wid  = tid >> 5;
    const int wm   = wid & 3;
    const int wn   = wid >> 2;
    const int bid  = blockIdx.x;
    const uint32_t alo = a_lane_off(lane);

    if (bid < 32) {
        // ================= GRU chain: 64 cols =================
        __half* Ws = smh;                               // [64][WSTRH_G]
        const uint32_t ws_u32 = smb;
        const uint32_t as_u32 = smb + 64 * WSTRH_G * 2; // 4 x [128][ASTRH]
        float* Cs = (float*)(smh + 64 * WSTRH_G);       // staging, stride CSTR
        const uint32_t blo = b_lane_off(lane, WSTRH_G);
        const int n0 = bid * 64;

        for (int i = tid; i < 64 * 64; i += NTH) {
            const int r = i >> 6, c = (i & 63) * 8;
            *(uint4*)(Ws + r * WSTRH_G + c) = *(const uint4*)(g_Wg1h + (size_t)(n0 + r) * HH + c);
        }
        __syncthreads();

        for (int t = 1; t < TSTEPS; ++t) {
            const __half* Abh  = (t == 1) ? g_zh : g_xh + (size_t)((t - 1) & 1) * BB * HH;
            const float*  hp32 = (t == 1) ? z    : g_x  + (size_t)((t - 1) & 1) * BB * HH;
            float*  xo32 = g_x    + (size_t)(t & 1) * BB * HH;
            __half* xoh  = g_xh   + (size_t)(t & 1) * BB * HH;
            __half* so   = g_seqh + (size_t)t * BB * HH;

            float hp[4];
#pragma unroll
            for (int s = 0; s < 4; s++) {
                const int it = tid + s * NTH;
                hp[s] = hp32[(size_t)(it >> 4) * HH + (n0 >> 2) + (it & 15)];
            }

            float4 acc[2][2];
#pragma unroll
            for (int mi = 0; mi < 2; mi++)
#pragma unroll
                for (int ni = 0; ni < 2; ni++) acc[mi][ni] = make_float4(0.f, 0.f, 0.f, 0.f);

            chain_mainloop<2>(8, Abh, HH, as_u32, ws_u32, WSTRH_G,
                              alo, blo, wm, wn, tid, acc);

#pragma unroll
            for (int mi = 0; mi < 2; mi++) {
#pragma unroll
                for (int ni = 0; ni < 2; ni++) {
                    const int r = wm * 32 + mi * 16 + (lane >> 2);
                    const int c = wn * 16 + ni * 8 + 2 * (lane & 3);
                    const float b0 = g_bg[n0 + c], b1 = g_bg[n0 + c + 1];
                    Cs[r * CSTR + c]           = acc[mi][ni].x + b0;
                    Cs[r * CSTR + c + 1]       = acc[mi][ni].y + b1;
                    Cs[(r + 8) * CSTR + c]     = acc[mi][ni].z + b0;
                    Cs[(r + 8) * CSTR + c + 1] = acc[mi][ni].w + b1;
                }
            }
            __syncthreads();

#pragma unroll
            for (int s = 0; s < 4; s++) {
                const int it  = tid + s * NTH;
                const int u   = it & 15;
                const int row = it >> 4;
                const int jg  = (n0 >> 2) + u;
                const float4 cv = *(const float4*)(Cs + row * CSTR + 4 * u);
                const float rg = sigf(cv.x);
                const float zg = sigf(cv.y);
                const float nn = tanhf(cv.z + rg * cv.w);
                const float xn = (1.f - zg) * nn + zg * hp[s];
                const int oi = row * HH + jg;
                xo32[oi] = xn;
                xoh[oi]  = __float2half_rn(xn);
                so[oi]   = __float2half_rn(fmaxf(xn, 0.f));
            }

            bar_arrive(g_bar_gru);
            if (t < TSTEPS - 1) {
                wait_ge(g_bar_gru, 32u * (unsigned)t);
                if (t == 1) {
                    for (int i = tid; i < 64 * 64; i += NTH) {
                        const int r = i >> 6, c = (i & 63) * 8;
                        *(uint4*)(Ws + r * WSTRH_G + c) =
                            *(const uint4*)(g_Wgh + (size_t)(n0 + r) * HH + c);
                    }
                    __syncthreads();
                }
            }
        }
        fc_worker(smb, fcb, out);

    } else if (bid < 64) {
        // ================= XG: 128 cols =================
        __half* Ws = smh;                                // [128][WSTRH_G]
        const uint32_t ws_u32 = smb;
        const uint32_t as_u32 = smb + 128 * WSTRH_G * 2;
        const uint32_t blo = b_lane_off(lane, WSTRH_G);
        const int n0 = (bid - 32) * 128;

        for (int i = tid; i < 128 * 64; i += NTH) {
            const int r = i >> 6, c = (i & 63) * 8;
            *(uint4*)(Ws + r * WSTRH_G + c) = *(const uint4*)(g_Wihlh + (size_t)(n0 + r) * HH + c);
        }
        __syncthreads();

        for (int t = 1; t < TSTEPS; ++t) {
            wait_ge(g_bar_gru, 32u * (unsigned)t);
            const __half* Abh = g_seqh + (size_t)t * BB * HH;

            float4 acc[2][4];
#pragma unroll
            for (int mi = 0; mi < 2; mi++)
#pragma unroll
                for (int ni = 0; ni < 4; ni++) acc[mi][ni] = make_float4(0.f, 0.f, 0.f, 0.f);

            chain_mainloop<4>(8, Abh, HH, as_u32, ws_u32, WSTRH_G,
                              alo, blo, wm, wn, tid, acc);

#pragma unroll
            for (int mi = 0; mi < 2; mi++) {
#pragma unroll
                for (int ni = 0; ni < 4; ni++) {
                    const int r   = wm * 32 + mi * 16 + (lane >> 2);
                    const int col = n0 + wn * 32 + ni * 8 + 2 * (lane & 3);
                    const float b0 = g_bl[col], b1 = g_bl[col + 1];
                    float* o0 = g_Xg + ((size_t)t * BB + r) * 4096 + col;
                    float* o1 = g_Xg + ((size_t)t * BB + r + 8) * 4096 + col;
                    *(float2*)o0 = make_float2(acc[mi][ni].x + b0, acc[mi][ni].y + b1);
                    *(float2*)o1 = make_float2(acc[mi][ni].z + b0, acc[mi][ni].w + b1);
                }
            }
            bar_arrive(g_bar_xg);
        }
        fc_worker(smb, fcb, out);

    } else if (bid < 128) {
        // ================= LSTM chain: 64 cols =================
        __half* Ws = smh;                                // [64][WSTRH_L]
        const uint32_t ws_u32 = smb;
        const uint32_t as_u32 = smb + 64 * WSTRH_L * 2;
        float* Cs = (float*)(smh + 64 * WSTRH_L);        // staging, stride CSTR
        const uint32_t blo = b_lane_off(lane, WSTRH_L);
        const int n0 = (bid - 64) * 64;

        for (int i = tid; i < 64 * 128; i += NTH) {
            const int r = i >> 7, c = (i & 127) * 8;
            *(uint4*)(Ws + r * WSTRH_L + c) = *(const uint4*)(g_Whhlh + (size_t)(n0 + r) * LL + c);
        }
        __syncthreads();

        for (int t = 0; t < TSTEPS; ++t) {
            if (t >= 1)
                wait_ge2(g_bar_xg, 32u * (unsigned)t, g_bar_lstm, 64u * (unsigned)t);

            const __half* Abh = g_hh + (size_t)(t & 1) * BB * LL;
            __half* hoh       = g_hh + (size_t)((t + 1) & 1) * BB * LL;

            float4 xg[4];
            float  cc[4];
#pragma unroll
            for (int s = 0; s < 4; s++) {
                const int it  = tid + s * NTH;
                const int row = it >> 4;
                const int u   = it & 15;
                xg[s] = *(const float4*)(g_Xg + ((size_t)t * BB + row) * 4096 + n0 + 4 * u);
                cc[s] = g_c[row * LL + (n0 >> 2) + u];
            }

            float4 acc[2][2];
#pragma unroll
            for (int mi = 0; mi < 2; mi++)
#pragma unroll
                for (int ni = 0; ni < 2; ni++) acc[mi][ni] = make_float4(0.f, 0.f, 0.f, 0.f);

            if (t >= 1)
                chain_mainloop<2>(16, Abh, LL, as_u32, ws_u32, WSTRH_L,
                                  alo, blo, wm, wn, tid, acc);

#pragma unroll
            for (int mi = 0; mi < 2; mi++) {
#pragma unroll
                for (int ni = 0; ni < 2; ni++) {
                    const int r = wm * 32 + mi * 16 + (lane >> 2);
                    const int c = wn * 16 + ni * 8 + 2 * (lane & 3);
                    Cs[r * CSTR + c]           = acc[mi][ni].x;
                    Cs[r * CSTR + c + 1]       = acc[mi][ni].y;
                    Cs[(r + 8) * CSTR + c]     = acc[mi][ni].z;
                    Cs[(r + 8) * CSTR + c + 1] = acc[mi][ni].w;
                }
            }
            __syncthreads();

#pragma unroll
            for (int s = 0; s < 4; s++) {
                const int it  = tid + s * NTH;
                const int u   = it & 15;
                const int row = it >> 4;
                const int jg  = (n0 >> 2) + u;
                const float4 cv = *(const float4*)(Cs + row * CSTR + 4 * u);
                const float ig = sigf(cv.x + xg[s].x);
                const float fg = sigf(cv.y + xg[s].y);
                const float gg = tanhf(cv.z + xg[s].z);
                const float og = sigf(cv.w + xg[s].w);
                const int ci = row * LL + jg;
                const float cn = fg * cc[s] + ig * gg;
                g_c[ci] = cn;
                const float hn = og * tanhf(cn);
                hoh[ci] = __float2half_rn(hn);
                g_hsh[((size_t)t * BB + row) * LL + jg] = __float2half_rn(hn);
            }

            bar_arrive(g_bar_lstm);
        }
        fc_worker(smb, fcb, out);

    } else {
        fc_worker(smb, fcb, out);
    }
}

// ---------------- prep kernels ----------------
__global__ void prep_gru(const float* __restrict__ Wih, const float* __restrict__ Whh,
                         const float* __restrict__ bih, const float* __restrict__ bhh) {
    const int idx = blockIdx.x * blockDim.x + threadIdx.x;
    if (idx < 2048 * 512) {
        const int row = idx >> 9, k = idx & 511;
        const int j = row >> 2, g = row & 3;
        float wg, w1;
        if (g == 0)      { wg = Wih[j * 512 + k] + Whh[j * 512 + k];                 w1 = Whh[j * 512 + k]; }
        else if (g == 1) { wg = Wih[(512 + j) * 512 + k] + Whh[(512 + j) * 512 + k]; w1 = Whh[(512 + j) * 512 + k]; }
        else if (g == 2) { wg = Wih[(1024 + j) * 512 + k];                           w1 = 0.f; }
        else             { wg = Whh[(1024 + j) * 512 + k];                           w1 = wg; }
        g_Wgh[idx]  = __float2half_rn(wg);
        g_Wg1h[idx] = __float2half_rn(w1);
    }
    if (idx < 2048) {
        const int j = idx >> 2, g = idx & 3;
        float b;
        if (g == 0)      b = bih[j] + bhh[j];
        else if (g == 1) b = bih[512 + j] + bhh[512 + j];
        else if (g == 2) b = bih[1024 + j];
        else             b = bhh[1024 + j];
        g_bg[idx] = b;
    }
}

__global__ void prep_lstm(const float* __restrict__ Wih, const float* __restrict__ Whh,
                          const float* __restrict__ bih, const float* __restrict__ bhh,
                          const float* __restrict__ fcW) {
    const int idx = blockIdx.x * blockDim.x + threadIdx.x;
    if (idx < 4096 * 1024) {
        const int row = idx >> 10, k = idx & 1023;
        const int j = row >> 2, p = row & 3;
        g_Whhlh[idx] = __float2half_rn(Whh[(size_t)(p * 1024 + j) * 1024 + k]);
    }
    if (idx < 4096 * 512) {
        const int row = idx >> 9, k = idx & 511;
        const int j = row >> 2, p = row & 3;
        g_Wihlh[idx] = __float2half_rn(Wih[(size_t)(p * 1024 + j) * 512 + k]);
    }
    if (idx < 1024 * 1024) {
        g_fcWh[idx] = __float2half_rn(fcW[idx]);
    }
    if (idx < 4096) {
        const int j = idx >> 2, p = idx & 3;
        g_bl[idx] = bih[p * 1024 + j] + bhh[p * 1024 + j];
    }
}

__global__ void prep_zero(const float* __restrict__ z) {
    const int idx = blockIdx.x * blockDim.x + threadIdx.x;
    if (idx < BB * LL) { g_hh[idx] = __float2half_rn(0.f); g_c[idx] = 0.f; }
    if (idx < BB * HH) { g_zh[idx] = __float2half_rn(z[idx]); }
    if (idx < BB * 4096) { g_Xg[idx] = g_bl[idx & 4095]; }
    if (idx == 0) { g_bar_gru[0] = 0u; g_bar_xg[0] = 0u; g_bar_lstm[0] = 0u; g_fc_cnt[0] = 0u; }
}

// ---------------- host launcher ----------------
extern "C" void kernel_launch(void* const* d_in, const int* in_sizes, int n_in,
                              void* d_out, int out_size) {
    const float* z    = (const float*)d_in[0];
    const float* gWih = (const float*)d_in[2];
    const float* gWhh = (const float*)d_in[3];
    const float* gbih = (const float*)d_in[4];
    const float* gbhh = (const float*)d_in[5];
    const float* lWih = (const float*)d_in[6];
    const float* lWhh = (const float*)d_in[7];
    const float* lbih = (const float*)d_in[8];
    const float* lbhh = (const float*)d_in[9];
    const float* fcW  = (const float*)d_in[10];
    const float* fcb  = (const float*)d_in[11];
    float* out = (float*)d_out;

    cudaFuncSetAttribute(fused_persist, cudaFuncAttributeMaxDynamicSharedMemorySize, SMEM_FUSED);

    prep_gru <<<(2048 * 512 + 255) / 256, 256>>>(gWih, gWhh, gbih, gbhh);
    prep_lstm<<<(4096 * 1024 + 255) / 256, 256>>>(lWih, lWhh, lbih, lbhh, fcW);
    prep_zero<<<(BB * 4096 + 255) / 256, 256>>>(z);

    // fused pipeline: GRU | XG | LSTM | FC on disjoint CTA sets,
    // 4-deep cp.async ring hides A-tile L2 latency in every mainloop
    fused_persist<<<148, NTH, SMEM_FUSED>>>(z, fcb, out);
}